// round 5
// baseline (speedup 1.0000x reference)
#include <cuda_runtime.h>
#include <math.h>

// Problem dims
constexpr int NB = 64;     // batch
constexpr int NT = 256;    // time
constexpr int ND = 1024;   // input dim
constexpr int NH = 1024;   // hidden
constexpr int NG = 4096;   // 4*NH (gates i,f,g,o)

// Step-kernel tiling
constexpr int JT     = 16;       // h-columns per block tile (=> 64 gate cols)
constexpr int NJT    = NH / JT;  // 64 j-tiles
constexpr int NSPLIT = 4;        // K splits per layer-step
constexpr int BK     = 32;       // k-chunk

// ---------------------------------------------------------------------------
// Scratch state (device globals: allocation-free per harness rules)
// ---------------------------------------------------------------------------
__device__ float g_xpre[(size_t)NT * NB * NG];  // x @ Wx0 + b0  (256 MB)
__device__ float g_h0[2][NB * NH];              // ping-pong by t parity
__device__ float g_h1[2][NB * NH];
__device__ float g_c0[NB * NH];
__device__ float g_c1[NB * NH];
__device__ float g_part[NSPLIT][NB * NG];       // split-K partial gates (4 MB)
__device__ int   g_cnt[2][NJT];                 // per (layer, j-tile) arrival counters

// ---------------------------------------------------------------------------
// Packed f32x2 helpers (Blackwell packed fp32: 2x FFMA throughput)
// ---------------------------------------------------------------------------
__device__ __forceinline__ unsigned long long dup2(float v) {
    unsigned long long r;
    asm("mov.b64 %0, {%1, %1};" : "=l"(r) : "f"(v));
    return r;
}
__device__ __forceinline__ void fma2(unsigned long long& acc,
                                     unsigned long long a, unsigned long long b) {
    asm("fma.rn.f32x2 %0, %1, %2, %0;" : "+l"(acc) : "l"(a), "l"(b));
}
__device__ __forceinline__ void unpack2(unsigned long long v, float& lo, float& hi) {
    asm("mov.b64 {%0, %1}, %2;" : "=f"(lo), "=f"(hi) : "l"(v));
}
__device__ __forceinline__ unsigned long long pack2(float lo, float hi) {
    unsigned long long r;
    asm("mov.b64 %0, {%1, %2};" : "=l"(r) : "f"(lo), "f"(hi));
    return r;
}
__device__ __forceinline__ float sigmoidf_(float x) { return 1.0f / (1.0f + expf(-x)); }

// ---------------------------------------------------------------------------
// Zero recurrent state + counters (graph replays reuse device globals)
// ---------------------------------------------------------------------------
__global__ void init_state_kernel() {
    int i = blockIdx.x * blockDim.x + threadIdx.x;
    if (i < NB * NH) {
        g_h0[0][i] = 0.f; g_h0[1][i] = 0.f;
        g_h1[0][i] = 0.f; g_h1[1][i] = 0.f;
        g_c0[i] = 0.f;    g_c1[i] = 0.f;
    }
    if (i < 2 * NJT) ((int*)g_cnt)[i] = 0;
}

// ---------------------------------------------------------------------------
// Precompute: Xpre[(t*NB+b)][n] = sum_k x[b][t][k] * Wx0[k][n] + b0[n]
// (unchanged from prior passing round)
// ---------------------------------------------------------------------------
__global__ __launch_bounds__(256) void precompute_kernel(
    const float* __restrict__ x, const float* __restrict__ Wx0,
    const float* __restrict__ b0)
{
    constexpr int PBK = 16;
    __shared__ float As[PBK][132];
    __shared__ float Ws[PBK][64];

    const int tid = threadIdx.x;
    const int tc = tid & 15;
    const int tr = tid >> 4;
    const int col0 = blockIdx.x * 64;
    const int row0 = blockIdx.y * 128;

    unsigned long long acc[8][2];
#pragma unroll
    for (int i = 0; i < 8; i++) { acc[i][0] = 0ull; acc[i][1] = 0ull; }

    for (int k0 = 0; k0 < ND; k0 += PBK) {
#pragma unroll
        for (int i = 0; i < 2; i++) {
            int idx = tid + i * 256;
            int r   = idx & 127;
            int kq  = (idx >> 7) << 2;
            int grow = row0 + r;
            int tt = grow >> 6;
            int bb = grow & 63;
            float4 v = *(const float4*)&x[((size_t)bb * NT + tt) * ND + k0 + kq];
            As[kq + 0][r] = v.x; As[kq + 1][r] = v.y;
            As[kq + 2][r] = v.z; As[kq + 3][r] = v.w;
        }
        {
            int kk = tid >> 4;
            int nq = (tid & 15) << 2;
            *(float4*)&Ws[kk][nq] =
                *(const float4*)&Wx0[(size_t)(k0 + kk) * NG + col0 + nq];
        }
        __syncthreads();

#pragma unroll
        for (int kk = 0; kk < PBK; kk++) {
            float4 a0 = *(const float4*)&As[kk][tr * 8];
            float4 a1 = *(const float4*)&As[kk][tr * 8 + 4];
            float4 wv = *(const float4*)&Ws[kk][tc * 4];
            unsigned long long w01 = pack2(wv.x, wv.y);
            unsigned long long w23 = pack2(wv.z, wv.w);
            float ar[8] = {a0.x, a0.y, a0.z, a0.w, a1.x, a1.y, a1.z, a1.w};
#pragma unroll
            for (int i = 0; i < 8; i++) {
                unsigned long long ad = dup2(ar[i]);
                fma2(acc[i][0], ad, w01);
                fma2(acc[i][1], ad, w23);
            }
        }
        __syncthreads();
    }

    const int c = col0 + tc * 4;
    float4 bb4 = *(const float4*)&b0[c];
#pragma unroll
    for (int i = 0; i < 8; i++) {
        int grow = row0 + tr * 8 + i;
        float v0, v1, v2, v3;
        unpack2(acc[i][0], v0, v1);
        unpack2(acc[i][1], v2, v3);
        float4 o;
        o.x = v0 + bb4.x; o.y = v1 + bb4.y; o.z = v2 + bb4.z; o.w = v3 + bb4.w;
        *(float4*)&g_xpre[(size_t)grow * NG + c] = o;
    }
}

// ---------------------------------------------------------------------------
// One LSTM layer step: split-K GEMM + last-block-fused cell update.
//   layer 0: gates = Xpre[t] + h0_prev @ Wh0            (K=1024, 4 splits x 256)
//   layer 1: gates = b1 + h0_new @ Wx1 + h1_prev @ Wh1  (K=2048, 4 splits x 512)
// grid (64 j-tiles, 4 splits) = 256 blocks x 256 threads.
// Block tile: 64 rows x 64 gate-cols (j-tile of 16 h-cols, gates i/f/g/o grouped).
// Thread tile: 8 rows x 2 cols; row-pair f32x2 accumulators.
// Double-buffered smem, BK=32, one barrier per chunk.
// Last split block per j-tile (atomic counter) reduces partials + activations.
// ---------------------------------------------------------------------------
__global__ __launch_bounds__(256, 2) void lstm_step_kernel(
    int layer, int t,
    const float* __restrict__ W1p,   // Wh0 (L0) or Wx1 (L1)
    const float* __restrict__ W2p,   // Wh1 (L1) or null
    const float* __restrict__ biasp) // b1 (L1) or null
{
    __shared__ float As[2][BK][64];  // [buf][k][row]
    __shared__ float Ws[2][BK][64];  // [buf][k][blockcol]
    __shared__ int s_last;

    const int tid = threadIdx.x;     // 256
    const int tr  = tid & 7;         // 8 row-threads  * 8 rows = 64
    const int tc  = tid >> 3;        // 32 col-threads * 2 cols = 64
    const int jt  = blockIdx.x;      // 0..63
    const int sp  = blockIdx.y;      // 0..3
    const int j0  = jt * JT;

    const int cur = t & 1, nxt = cur ^ 1;
    const float* A;
    const float* W;
    int k0, Ksp;
    float* cS; float* hOut;
    if (layer == 0) {
        Ksp = ND / NSPLIT;                       // 256
        A = g_h0[cur]; W = W1p; k0 = sp * Ksp;
        cS = g_c0; hOut = g_h0[nxt];
    } else {
        Ksp = 2048 / NSPLIT;                     // 512
        if (sp < 2) { A = g_h0[nxt]; W = W1p; k0 = sp * Ksp; }        // h0 (current t)
        else        { A = g_h1[cur]; W = W2p; k0 = (sp - 2) * Ksp; }  // h1 (prev t)
        cS = g_c1; hOut = g_h1[nxt];
    }
    const int NCH = Ksp / BK;   // 8 (L0) or 16 (L1)

    unsigned long long acc[4][2];
#pragma unroll
    for (int p = 0; p < 4; p++) { acc[p][0] = 0ull; acc[p][1] = 0ull; }

    float4 aSt[2], wSt[2];

    // ---- global -> register load of chunk ch ----
    auto ldg_chunk = [&](int ch) {
        const int kc = k0 + ch * BK;
#pragma unroll
        for (int i = 0; i < 2; i++) {
            int idx = tid + i * 256;            // 0..511
            int r   = idx & 63;
            int kq  = (idx >> 6) << 2;          // 0..28 step 4
            aSt[i] = *(const float4*)&A[(size_t)r * NH + kc + kq];
        }
#pragma unroll
        for (int i = 0; i < 2; i++) {
            int idx = tid + i * 256;
            int kk  = idx >> 4;                 // 0..31
            int rem = idx & 15;                 // block col = rem*4
            int g   = rem >> 2;
            int jq  = (rem & 3) << 2;
            wSt[i] = *(const float4*)&W[(size_t)(kc + kk) * NG + g * NH + j0 + jq];
        }
    };
    // ---- register -> smem store into buffer b ----
    auto sts_chunk = [&](int b) {
#pragma unroll
        for (int i = 0; i < 2; i++) {
            int idx = tid + i * 256;
            int r   = idx & 63;
            int kq  = (idx >> 6) << 2;
            As[b][kq + 0][r] = aSt[i].x; As[b][kq + 1][r] = aSt[i].y;
            As[b][kq + 2][r] = aSt[i].z; As[b][kq + 3][r] = aSt[i].w;
        }
#pragma unroll
        for (int i = 0; i < 2; i++) {
            int idx = tid + i * 256;
            int kk  = idx >> 4;
            int rem = idx & 15;
            *(float4*)&Ws[b][kk][rem << 2] = wSt[i];
        }
    };

    ldg_chunk(0);
    sts_chunk(0);
    __syncthreads();

    int buf = 0;
    for (int ch = 0; ch < NCH; ch++) {
        if (ch + 1 < NCH) ldg_chunk(ch + 1);

        // compute on buf
#pragma unroll
        for (int kk = 0; kk < BK; kk++) {
            ulonglong2 av0 = *(const ulonglong2*)&As[buf][kk][tr * 8];
            ulonglong2 av1 = *(const ulonglong2*)&As[buf][kk][tr * 8 + 4];
            float2 wv = *(const float2*)&Ws[buf][kk][tc * 2];
            unsigned long long wd0 = dup2(wv.x);
            unsigned long long wd1 = dup2(wv.y);
            fma2(acc[0][0], av0.x, wd0); fma2(acc[0][1], av0.x, wd1);
            fma2(acc[1][0], av0.y, wd0); fma2(acc[1][1], av0.y, wd1);
            fma2(acc[2][0], av1.x, wd0); fma2(acc[2][1], av1.x, wd1);
            fma2(acc[3][0], av1.y, wd0); fma2(acc[3][1], av1.y, wd1);
        }

        if (ch + 1 < NCH) sts_chunk(buf ^ 1);
        __syncthreads();
        buf ^= 1;
    }

    // ---- write split partial ----
    {
        float* P = g_part[sp];
        const int bc0 = tc * 2;                     // block col (even)
        const int gcol = (bc0 >> 4) * NH + j0 + (bc0 & 15);
#pragma unroll
        for (int p = 0; p < 4; p++) {
            int r = tr * 8 + p * 2;
            float l0, h0v, l1, h1v;
            unpack2(acc[p][0], l0, h0v);   // col bc0:   rows r, r+1
            unpack2(acc[p][1], l1, h1v);   // col bc0+1
            float2 e = make_float2(l0, l1);
            float2 o = make_float2(h0v, h1v);
            *(float2*)&P[(size_t)r * NG + gcol]       = e;
            *(float2*)&P[(size_t)(r + 1) * NG + gcol] = o;
        }
    }

    // ---- last-block-done: fused cell update for this j-tile ----
    __threadfence();
    __syncthreads();
    if (tid == 0) {
        int v = atomicAdd(&g_cnt[layer][jt], 1);
        s_last = (v == NSPLIT - 1);
    }
    __syncthreads();

    if (s_last) {
        __threadfence();
        // 64 rows x 16 h-cols = 1024 elems, 4 per thread
#pragma unroll
        for (int u = 0; u < 4; u++) {
            int idx = tid + (u << 8);
            int r  = idx >> 4;          // batch row
            int jj = idx & 15;
            int col = j0 + jj;
            float gi = 0.f, gf = 0.f, gg = 0.f, go = 0.f;
#pragma unroll
            for (int s = 0; s < NSPLIT; s++) {
                const float* P = g_part[s] + (size_t)r * NG + col;
                gi += P[0]; gf += P[NH]; gg += P[2 * NH]; go += P[3 * NH];
            }
            if (layer == 0) {
                const float* xp = g_xpre + (size_t)t * NB * NG + (size_t)r * NG + col;
                gi += xp[0]; gf += xp[NH]; gg += xp[2 * NH]; go += xp[3 * NH];
            } else {
                const float* bp = biasp + col;
                gi += bp[0]; gf += bp[NH]; gg += bp[2 * NH]; go += bp[3 * NH];
            }
            int ci = r * NH + col;
            float cv = cS[ci];
            float is = sigmoidf_(gi), fs = sigmoidf_(gf);
            float gt = tanhf(gg),     os = sigmoidf_(go);
            float cn = fs * cv + is * gt;
            cS[ci]   = cn;
            hOut[ci] = os * tanhf(cn);
        }
        if (tid == 0) g_cnt[layer][jt] = 0;   // self-reset for next step / replay
    }
}

// ---------------------------------------------------------------------------
// Copy final top-layer hidden state to output. After t = NT-1 (odd), layer1
// wrote g_h1[nxt = 0].
// ---------------------------------------------------------------------------
__global__ void copy_out_kernel(float* __restrict__ out) {
    int i = blockIdx.x * blockDim.x + threadIdx.x;
    if (i < NB * NH) out[i] = g_h1[0][i];
}

// ---------------------------------------------------------------------------
// kernel_launch: graph-capturable, allocation-free, deterministic.
// Inputs: x, Wx0, Wh0, b0, Wx1, Wh1, b1. Output: h1 [64,1024] fp32.
// ---------------------------------------------------------------------------
extern "C" void kernel_launch(void* const* d_in, const int* in_sizes, int n_in,
                              void* d_out, int out_size) {
    const float* x   = (const float*)d_in[0];
    const float* Wx0 = (const float*)d_in[1];
    const float* Wh0 = (const float*)d_in[2];
    const float* b0  = (const float*)d_in[3];
    const float* Wx1 = (const float*)d_in[4];
    const float* Wh1 = (const float*)d_in[5];
    const float* b1  = (const float*)d_in[6];
    float* out = (float*)d_out;

    (void)in_sizes; (void)n_in; (void)out_size;

    init_state_kernel<<<(NB * NH + 255) / 256, 256>>>();

    // Phase 1: all-timestep input projection for layer 0
    precompute_kernel<<<dim3(NG / 64, (NT * NB) / 128), 256>>>(x, Wx0, b0);

    // Phase 2: sequential recurrence, 2 launches per timestep
    for (int t = 0; t < NT; t++) {
        lstm_step_kernel<<<dim3(NJT, NSPLIT), 256>>>(0, t, Wh0, nullptr, nullptr);
        lstm_step_kernel<<<dim3(NJT, NSPLIT), 256>>>(1, t, Wx1, Wh1, b1);
    }

    copy_out_kernel<<<(NB * NH + 1023) / 1024, 1024>>>(out);
}

// round 8
// speedup vs baseline: 1.8935x; 1.8935x over previous
#include <cuda_runtime.h>
#include <math.h>

// Problem dims
constexpr int NB = 64;     // batch
constexpr int NT = 256;    // time
constexpr int ND = 1024;   // input dim
constexpr int NH = 1024;   // hidden
constexpr int NG = 4096;   // 4*NH (gates i,f,g,o)

// Step-kernel tiling: block = 64 rows x 256 gate-cols (= 64 h-cols x 4 gates),
// 256 threads, 8x8 per thread, BK=16 double-buffered, split-K=8.
constexpr int JT     = 64;       // h-columns per block tile
constexpr int NJT    = NH / JT;  // 16 j-tiles
constexpr int NSPLIT = 8;        // K splits per layer-step
constexpr int BK     = 16;       // k-chunk

// ---------------------------------------------------------------------------
// Scratch state (device globals: allocation-free per harness rules)
// ---------------------------------------------------------------------------
__device__ float g_xpre[(size_t)NT * NB * NG];  // x @ Wx0 + b0  (256 MB)
__device__ float g_h0[2][NB * NH];              // ping-pong by t parity
__device__ float g_h1[2][NB * NH];
__device__ float g_c0[NB * NH];
__device__ float g_c1[NB * NH];
__device__ float g_part[NSPLIT][NB * NG];       // split-K partial gates (8 MB)
__device__ int   g_cnt[2][NJT];                 // per (layer, j-tile) counters

// ---------------------------------------------------------------------------
// Packed f32x2 helpers (Blackwell packed fp32: 2x FFMA throughput)
// ---------------------------------------------------------------------------
__device__ __forceinline__ unsigned long long dup2(float v) {
    unsigned long long r;
    asm("mov.b64 %0, {%1, %1};" : "=l"(r) : "f"(v));
    return r;
}
__device__ __forceinline__ void fma2(unsigned long long& acc,
                                     unsigned long long a, unsigned long long b) {
    asm("fma.rn.f32x2 %0, %1, %2, %0;" : "+l"(acc) : "l"(a), "l"(b));
}
__device__ __forceinline__ void unpack2(unsigned long long v, float& lo, float& hi) {
    asm("mov.b64 {%0, %1}, %2;" : "=f"(lo), "=f"(hi) : "l"(v));
}
__device__ __forceinline__ unsigned long long pack2(float lo, float hi) {
    unsigned long long r;
    asm("mov.b64 %0, {%1, %2};" : "=l"(r) : "f"(lo), "f"(hi));
    return r;
}
__device__ __forceinline__ float sigmoidf_(float x) { return 1.0f / (1.0f + expf(-x)); }

// ---------------------------------------------------------------------------
// Zero recurrent state + counters (graph replays reuse device globals)
// ---------------------------------------------------------------------------
__global__ void init_state_kernel() {
    int i = blockIdx.x * blockDim.x + threadIdx.x;
    if (i < NB * NH) {
        g_h0[0][i] = 0.f; g_h0[1][i] = 0.f;
        g_h1[0][i] = 0.f; g_h1[1][i] = 0.f;
        g_c0[i] = 0.f;    g_c1[i] = 0.f;
    }
    if (i < 2 * NJT) ((int*)g_cnt)[i] = 0;
}

// ---------------------------------------------------------------------------
// Precompute: Xpre[(t*NB+b)][n] = sum_k x[b][t][k] * Wx0[k][n] + b0[n]
// (unchanged from prior passing rounds)
// ---------------------------------------------------------------------------
__global__ __launch_bounds__(256) void precompute_kernel(
    const float* __restrict__ x, const float* __restrict__ Wx0,
    const float* __restrict__ b0)
{
    constexpr int PBK = 16;
    __shared__ float As[PBK][132];
    __shared__ float Ws[PBK][64];

    const int tid = threadIdx.x;
    const int tc = tid & 15;
    const int tr = tid >> 4;
    const int col0 = blockIdx.x * 64;
    const int row0 = blockIdx.y * 128;

    unsigned long long acc[8][2];
#pragma unroll
    for (int i = 0; i < 8; i++) { acc[i][0] = 0ull; acc[i][1] = 0ull; }

    for (int k0 = 0; k0 < ND; k0 += PBK) {
#pragma unroll
        for (int i = 0; i < 2; i++) {
            int idx = tid + i * 256;
            int r   = idx & 127;
            int kq  = (idx >> 7) << 2;
            int grow = row0 + r;
            int tt = grow >> 6;
            int bb = grow & 63;
            float4 v = *(const float4*)&x[((size_t)bb * NT + tt) * ND + k0 + kq];
            As[kq + 0][r] = v.x; As[kq + 1][r] = v.y;
            As[kq + 2][r] = v.z; As[kq + 3][r] = v.w;
        }
        {
            int kk = tid >> 4;
            int nq = (tid & 15) << 2;
            *(float4*)&Ws[kk][nq] =
                *(const float4*)&Wx0[(size_t)(k0 + kk) * NG + col0 + nq];
        }
        __syncthreads();

#pragma unroll
        for (int kk = 0; kk < PBK; kk++) {
            float4 a0 = *(const float4*)&As[kk][tr * 8];
            float4 a1 = *(const float4*)&As[kk][tr * 8 + 4];
            float4 wv = *(const float4*)&Ws[kk][tc * 4];
            unsigned long long w01 = pack2(wv.x, wv.y);
            unsigned long long w23 = pack2(wv.z, wv.w);
            float ar[8] = {a0.x, a0.y, a0.z, a0.w, a1.x, a1.y, a1.z, a1.w};
#pragma unroll
            for (int i = 0; i < 8; i++) {
                unsigned long long ad = dup2(ar[i]);
                fma2(acc[i][0], ad, w01);
                fma2(acc[i][1], ad, w23);
            }
        }
        __syncthreads();
    }

    const int c = col0 + tc * 4;
    float4 bb4 = *(const float4*)&b0[c];
#pragma unroll
    for (int i = 0; i < 8; i++) {
        int grow = row0 + tr * 8 + i;
        float v0, v1, v2, v3;
        unpack2(acc[i][0], v0, v1);
        unpack2(acc[i][1], v2, v3);
        float4 o;
        o.x = v0 + bb4.x; o.y = v1 + bb4.y; o.z = v2 + bb4.z; o.w = v3 + bb4.w;
        *(float4*)&g_xpre[(size_t)grow * NG + c] = o;
    }
}

// ---------------------------------------------------------------------------
// One LSTM layer step: split-K GEMM + last-block-fused cell update.
//   layer 0: gates = Xpre[t] + h0_prev @ Wh0            (K=1024, 8 splits x 128)
//   layer 1: gates = b1 + h0_new @ Wx1 + h1_prev @ Wh1  (K=2048, 8 splits x 256)
// grid (16 j-tiles, 8 splits) = 128 blocks (single wave on 148 SMs).
// Block tile 64 rows x 256 gate-cols; thread tile 8x8 (1.0 MAC per smem byte:
// crossbar and FFMA2 pipe balanced at 128 MAC/cyc/SM).
// A-tile LDS is warp-uniform broadcast; W-tile LDS.128 phase-conflict-free.
// ---------------------------------------------------------------------------
__global__ __launch_bounds__(256, 1) void lstm_step_kernel(
    int layer, int t,
    const float* __restrict__ W1p,   // Wh0 (L0) or Wx1 (L1)
    const float* __restrict__ W2p,   // Wh1 (L1) or null
    const float* __restrict__ biasp) // b1 (L1) or null
{
    __shared__ __align__(16) float As[2][BK][64];    //  8 KB
    __shared__ __align__(16) float Ws[2][BK][256];   // 32 KB
    __shared__ int s_last;

    const int tid = threadIdx.x;     // 256
    const int tc  = tid & 31;        // 32 col-threads * 8 cols = 256
    const int tr  = tid >> 5;        // 8 row-threads * 8 rows = 64
    const int jt  = blockIdx.x;      // 0..15
    const int sp  = blockIdx.y;      // 0..7
    const int j0  = jt * JT;         // h-col base

    const int cur = t & 1, nxt = cur ^ 1;
    const float* A;
    const float* W;
    int k0, Ksp;
    float* cS; float* hOut;
    if (layer == 0) {
        Ksp = ND / NSPLIT;                       // 128
        A = g_h0[cur]; W = W1p; k0 = sp * Ksp;
        cS = g_c0; hOut = g_h0[nxt];
    } else {
        Ksp = 2048 / NSPLIT;                     // 256
        if (sp < 4) { A = g_h0[nxt]; W = W1p; k0 = sp * Ksp; }        // h0 (cur t)
        else        { A = g_h1[cur]; W = W2p; k0 = (sp - 4) * Ksp; }  // h1 (prev t)
        cS = g_c1; hOut = g_h1[nxt];
    }
    const int NCH = Ksp / BK;   // 8 (L0) or 16 (L1)

    unsigned long long acc[4][8];   // 4 row-pairs x 8 cols
#pragma unroll
    for (int p = 0; p < 4; p++)
#pragma unroll
        for (int c = 0; c < 8; c++) acc[p][c] = 0ull;

    float4 aSt, wSt[4];

    // global -> register load of chunk ch
    auto ldg_chunk = [&](int ch) {
        const int kc = k0 + ch * BK;
        {
            int r  = tid & 63;
            int kq = (tid >> 6) << 2;            // 0,4,8,12
            aSt = *(const float4*)&A[(size_t)r * NH + kc + kq];
        }
#pragma unroll
        for (int i = 0; i < 4; i++) {
            int idx = tid + i * 256;             // 0..1023
            int kk  = idx >> 6;                  // 0..15
            int rem = idx & 63;
            wSt[i] = *(const float4*)
                &W[(size_t)(kc + kk) * NG + (rem >> 4) * NH + j0 + ((rem & 15) << 2)];
        }
    };
    // register -> smem store into buffer b
    auto sts_chunk = [&](int b) {
        {
            int r  = tid & 63;
            int kq = (tid >> 6) << 2;
            As[b][kq + 0][r] = aSt.x; As[b][kq + 1][r] = aSt.y;
            As[b][kq + 2][r] = aSt.z; As[b][kq + 3][r] = aSt.w;
        }
#pragma unroll
        for (int i = 0; i < 4; i++) {
            int idx = tid + i * 256;
            int kk  = idx >> 6;
            int rem = idx & 63;
            *(float4*)&Ws[b][kk][rem << 2] = wSt[i];
        }
    };

    ldg_chunk(0);
    sts_chunk(0);
    __syncthreads();

    int buf = 0;
    for (int ch = 0; ch < NCH; ch++) {
        if (ch + 1 < NCH) ldg_chunk(ch + 1);

#pragma unroll
        for (int kk = 0; kk < BK; kk++) {
            ulonglong2 a0 = *(const ulonglong2*)&As[buf][kk][tr * 8];
            ulonglong2 a1 = *(const ulonglong2*)&As[buf][kk][tr * 8 + 4];
            float4 w0 = *(const float4*)&Ws[buf][kk][tc * 4];
            float4 w1 = *(const float4*)&Ws[buf][kk][128 + tc * 4];
            unsigned long long wd[8] = {
                dup2(w0.x), dup2(w0.y), dup2(w0.z), dup2(w0.w),
                dup2(w1.x), dup2(w1.y), dup2(w1.z), dup2(w1.w)};
            unsigned long long ap[4] = {a0.x, a0.y, a1.x, a1.y};
#pragma unroll
            for (int p = 0; p < 4; p++)
#pragma unroll
                for (int c = 0; c < 8; c++) fma2(acc[p][c], ap[p], wd[c]);
        }

        if (ch + 1 < NCH) sts_chunk(buf ^ 1);
        __syncthreads();
        buf ^= 1;
    }

    // ---- write split partial (rows tr*8..tr*8+7, 2 col groups of 4) ----
    {
        float* P = g_part[sp];
#pragma unroll
        for (int p = 0; p < 4; p++) {
            int r0 = tr * 8 + p * 2;
#pragma unroll
            for (int G = 0; G < 2; G++) {
                float lo[4], hi[4];
#pragma unroll
                for (int j = 0; j < 4; j++) unpack2(acc[p][G * 4 + j], lo[j], hi[j]);
                int bc   = G * 128 + tc * 4;
                int gcol = (bc >> 6) * NH + j0 + (bc & 63);
                *(float4*)&P[(size_t)r0 * NG + gcol] =
                    make_float4(lo[0], lo[1], lo[2], lo[3]);
                *(float4*)&P[(size_t)(r0 + 1) * NG + gcol] =
                    make_float4(hi[0], hi[1], hi[2], hi[3]);
            }
        }
    }

    // ---- last-block-done: fused cell update for this j-tile ----
    __threadfence();
    __syncthreads();
    if (tid == 0) {
        int v = atomicAdd(&g_cnt[layer][jt], 1);
        s_last = (v == NSPLIT - 1);
    }
    __syncthreads();

    if (s_last) {
        __threadfence();
        // 64 rows x 64 h-cols = 4096 cells, 16 per thread
#pragma unroll 4
        for (int u = 0; u < 16; u++) {
            int idx = tid + (u << 8);
            int hc = idx & 63;
            int r  = idx >> 6;
            int col = j0 + hc;
            float gi = 0.f, gf = 0.f, gg = 0.f, go = 0.f;
#pragma unroll
            for (int s = 0; s < NSPLIT; s++) {
                const float* P = g_part[s] + (size_t)r * NG + col;
                gi += P[0]; gf += P[NH]; gg += P[2 * NH]; go += P[3 * NH];
            }
            if (layer == 0) {
                const float* xp = g_xpre + (size_t)t * NB * NG + (size_t)r * NG + col;
                gi += xp[0]; gf += xp[NH]; gg += xp[2 * NH]; go += xp[3 * NH];
            } else {
                const float* bp = biasp + col;
                gi += bp[0]; gf += bp[NH]; gg += bp[2 * NH]; go += bp[3 * NH];
            }
            int ci = r * NH + col;
            float cv = cS[ci];
            float is = sigmoidf_(gi), fs = sigmoidf_(gf);
            float gt = tanhf(gg),     os = sigmoidf_(go);
            float cn = fs * cv + is * gt;
            cS[ci]   = cn;
            hOut[ci] = os * tanhf(cn);
        }
        if (tid == 0) g_cnt[layer][jt] = 0;   // self-reset for next step / replay
    }
}

// ---------------------------------------------------------------------------
// Copy final top-layer hidden state to output. After t = NT-1 (odd), layer1
// wrote g_h1[nxt = 0].
// ---------------------------------------------------------------------------
__global__ void copy_out_kernel(float* __restrict__ out) {
    int i = blockIdx.x * blockDim.x + threadIdx.x;
    if (i < NB * NH) out[i] = g_h1[0][i];
}

// ---------------------------------------------------------------------------
// kernel_launch: graph-capturable, allocation-free, deterministic.
// Inputs: x, Wx0, Wh0, b0, Wx1, Wh1, b1. Output: h1 [64,1024] fp32.
// ---------------------------------------------------------------------------
extern "C" void kernel_launch(void* const* d_in, const int* in_sizes, int n_in,
                              void* d_out, int out_size) {
    const float* x   = (const float*)d_in[0];
    const float* Wx0 = (const float*)d_in[1];
    const float* Wh0 = (const float*)d_in[2];
    const float* b0  = (const float*)d_in[3];
    const float* Wx1 = (const float*)d_in[4];
    const float* Wh1 = (const float*)d_in[5];
    const float* b1  = (const float*)d_in[6];
    float* out = (float*)d_out;

    (void)in_sizes; (void)n_in; (void)out_size;

    init_state_kernel<<<(NB * NH + 255) / 256, 256>>>();

    // Phase 1: all-timestep input projection for layer 0
    precompute_kernel<<<dim3(NG / 64, (NT * NB) / 128), 256>>>(x, Wx0, b0);

    // Phase 2: sequential recurrence, 2 launches per timestep (1 wave each)
    for (int t = 0; t < NT; t++) {
        lstm_step_kernel<<<dim3(NJT, NSPLIT), 256>>>(0, t, Wh0, nullptr, nullptr);
        lstm_step_kernel<<<dim3(NJT, NSPLIT), 256>>>(1, t, Wx1, Wh1, b1);
    }

    copy_out_kernel<<<(NB * NH + 1023) / 1024, 1024>>>(out);
}

// round 10
// speedup vs baseline: 2.4233x; 1.2798x over previous
#include <cuda_runtime.h>
#include <math.h>
#include <stdint.h>

// Problem dims
constexpr int NB = 64;     // batch
constexpr int NT = 256;    // time
constexpr int ND = 1024;   // input dim
constexpr int NH = 1024;   // hidden
constexpr int NG = 4096;   // 4*NH (gates i,f,g,o)

// Step-kernel tiling: block = 64 rows x 512 gate-cols (= 128 h-cols x 4 gates),
// 512 threads, 8x8 per thread, BK=8 cp.async double-buffered, split-K=16.
constexpr int JT     = 128;      // h-columns per block tile
constexpr int NJT    = NH / JT;  // 8 j-tiles
constexpr int NSPLIT = 16;       // K splits per layer-step
constexpr int BK     = 8;        // k-chunk for W streaming

// ---------------------------------------------------------------------------
// Scratch state (device globals: allocation-free per harness rules)
// ---------------------------------------------------------------------------
__device__ float g_xpre[(size_t)NT * NB * NG];  // x @ Wx0 + b0  (256 MB)
__device__ float g_h0[2][NB * NH];              // ping-pong by t parity
__device__ float g_h1[2][NB * NH];
__device__ float g_c0[NB * NH];
__device__ float g_c1[NB * NH];
__device__ float g_part[NSPLIT][NB * NG];       // split-K partial gates (16 MB)
__device__ int   g_cnt[2][NJT];                 // monotonic per (layer,jtile)

// ---------------------------------------------------------------------------
// Packed f32x2 helpers (Blackwell packed fp32: 2x FFMA throughput)
// ---------------------------------------------------------------------------
__device__ __forceinline__ unsigned long long dup2(float v) {
    unsigned long long r;
    asm("mov.b64 %0, {%1, %1};" : "=l"(r) : "f"(v));
    return r;
}
__device__ __forceinline__ void fma2(unsigned long long& acc,
                                     unsigned long long a, unsigned long long b) {
    asm("fma.rn.f32x2 %0, %1, %2, %0;" : "+l"(acc) : "l"(a), "l"(b));
}
__device__ __forceinline__ void unpack2(unsigned long long v, float& lo, float& hi) {
    asm("mov.b64 {%0, %1}, %2;" : "=f"(lo), "=f"(hi) : "l"(v));
}
__device__ __forceinline__ unsigned long long pack2(float lo, float hi) {
    unsigned long long r;
    asm("mov.b64 %0, {%1, %2};" : "=l"(r) : "f"(lo), "f"(hi));
    return r;
}
__device__ __forceinline__ float sig_(float x)  { return 1.0f / (1.0f + __expf(-x)); }
__device__ __forceinline__ float tanh_(float x) {
    float e = __expf(2.0f * x);            // inf-safe: e=inf -> 1, e=0 -> -1
    return 1.0f - 2.0f / (e + 1.0f);
}
__device__ __forceinline__ void cp16(uint32_t dst, const void* src) {
    asm volatile("cp.async.cg.shared.global [%0], [%1], 16;" :: "r"(dst), "l"(src));
}

// ---------------------------------------------------------------------------
// Zero recurrent state + counters (graph replays reuse device globals)
// ---------------------------------------------------------------------------
__global__ void init_state_kernel() {
    int i = blockIdx.x * blockDim.x + threadIdx.x;
    if (i < NB * NH) {
        g_h0[0][i] = 0.f; g_h0[1][i] = 0.f;
        g_h1[0][i] = 0.f; g_h1[1][i] = 0.f;
        g_c0[i] = 0.f;    g_c1[i] = 0.f;
    }
    if (i < 2 * NJT) ((int*)g_cnt)[i] = 0;
}

// ---------------------------------------------------------------------------
// Precompute: Xpre[(t*NB+b)][n] = sum_k x[b][t][k] * Wx0[k][n] + b0[n]
// (unchanged from prior passing rounds)
// ---------------------------------------------------------------------------
__global__ __launch_bounds__(256) void precompute_kernel(
    const float* __restrict__ x, const float* __restrict__ Wx0,
    const float* __restrict__ b0)
{
    constexpr int PBK = 16;
    __shared__ float As[PBK][132];
    __shared__ float Ws[PBK][64];

    const int tid = threadIdx.x;
    const int tc = tid & 15;
    const int tr = tid >> 4;
    const int col0 = blockIdx.x * 64;
    const int row0 = blockIdx.y * 128;

    unsigned long long acc[8][2];
#pragma unroll
    for (int i = 0; i < 8; i++) { acc[i][0] = 0ull; acc[i][1] = 0ull; }

    for (int k0 = 0; k0 < ND; k0 += PBK) {
#pragma unroll
        for (int i = 0; i < 2; i++) {
            int idx = tid + i * 256;
            int r   = idx & 127;
            int kq  = (idx >> 7) << 2;
            int grow = row0 + r;
            int tt = grow >> 6;
            int bb = grow & 63;
            float4 v = *(const float4*)&x[((size_t)bb * NT + tt) * ND + k0 + kq];
            As[kq + 0][r] = v.x; As[kq + 1][r] = v.y;
            As[kq + 2][r] = v.z; As[kq + 3][r] = v.w;
        }
        {
            int kk = tid >> 4;
            int nq = (tid & 15) << 2;
            *(float4*)&Ws[kk][nq] =
                *(const float4*)&Wx0[(size_t)(k0 + kk) * NG + col0 + nq];
        }
        __syncthreads();

#pragma unroll
        for (int kk = 0; kk < PBK; kk++) {
            float4 a0 = *(const float4*)&As[kk][tr * 8];
            float4 a1 = *(const float4*)&As[kk][tr * 8 + 4];
            float4 wv = *(const float4*)&Ws[kk][tc * 4];
            unsigned long long w01 = pack2(wv.x, wv.y);
            unsigned long long w23 = pack2(wv.z, wv.w);
            float ar[8] = {a0.x, a0.y, a0.z, a0.w, a1.x, a1.y, a1.z, a1.w};
#pragma unroll
            for (int i = 0; i < 8; i++) {
                unsigned long long ad = dup2(ar[i]);
                fma2(acc[i][0], ad, w01);
                fma2(acc[i][1], ad, w23);
            }
        }
        __syncthreads();
    }

    const int c = col0 + tc * 4;
    float4 bb4 = *(const float4*)&b0[c];
#pragma unroll
    for (int i = 0; i < 8; i++) {
        int grow = row0 + tr * 8 + i;
        float v0, v1, v2, v3;
        unpack2(acc[i][0], v0, v1);
        unpack2(acc[i][1], v2, v3);
        float4 o;
        o.x = v0 + bb4.x; o.y = v1 + bb4.y; o.z = v2 + bb4.z; o.w = v3 + bb4.w;
        *(float4*)&g_xpre[(size_t)grow * NG + c] = o;
    }
}

// ---------------------------------------------------------------------------
// One LSTM layer step: split-K GEMM + cooperative j-tile reduction.
//   layer 0: gates = Xpre[t] + h0_prev @ Wh0            (K=1024, 16 splits x 64)
//   layer 1: gates = b1 + h0_new @ Wx1 + h1_prev @ Wh1  (K=2048, 16 splits x 128)
// grid (8 j-tiles, 16 splits) = 128 blocks, 512 thr (single wave, 4 warps/SMSP).
// A slice preloaded to smem [k][row] once; W streamed with cp.async (BK=8 x2).
// After partial writes, all 16 blocks of a j-tile rendezvous on a monotonic
// counter and each reduces a disjoint 4-row slice (deterministic order).
// ---------------------------------------------------------------------------
__global__ __launch_bounds__(512, 1) void lstm_step_kernel(
    int layer, int t,
    const float* __restrict__ W1p,   // Wh0 (L0) or Wx1 (L1)
    const float* __restrict__ W2p,   // Wh1 (L1) or null
    const float* __restrict__ biasp) // b1 (L1) or null
{
    extern __shared__ float sdyn[];
    float* Asl = sdyn;                       // [Ksp<=128][64]   (32 KB)
    float* Wsl = sdyn + 128 * 64;            // [2][BK][512]     (32 KB)

    const int tid = threadIdx.x;     // 512
    const int tc  = tid & 63;        // 64 col-threads * 8 cols = 512
    const int tr  = tid >> 6;        // 8 row-threads * 8 rows = 64
    const int jt  = blockIdx.x;      // 0..7
    const int sp  = blockIdx.y;      // 0..15
    const int j0  = jt * JT;         // h-col base

    const int cur = t & 1, nxt = cur ^ 1;
    const float* A;
    const float* W;
    int k0, Ksp;
    float* cS; float* hOut;
    if (layer == 0) {
        Ksp = ND / NSPLIT;                       // 64
        A = g_h0[cur]; W = W1p; k0 = sp * Ksp;
        cS = g_c0; hOut = g_h0[nxt];
    } else {
        Ksp = 2048 / NSPLIT;                     // 128
        if (sp < 8) { A = g_h0[nxt]; W = W1p; k0 = sp * Ksp; }        // h0 (cur t)
        else        { A = g_h1[cur]; W = W2p; k0 = (sp - 8) * Ksp; }  // h1 (prev t)
        cS = g_c1; hOut = g_h1[nxt];
    }
    const int NCH = Ksp / BK;   // 8 (L0) or 16 (L1)

    const uint32_t wbase = (uint32_t)__cvta_generic_to_shared(Wsl);

    // issue cp.async for W chunk ch into buffer b
    auto issueW = [&](int ch, int b) {
        const int kc = k0 + ch * BK;
#pragma unroll
        for (int i = 0; i < 2; i++) {
            int idx = tid + i * 512;             // 0..1023
            int kk  = idx >> 7;                  // 0..7
            int rem = idx & 127;                 // float4 group within 512 cols
            const float* src =
                &W[(size_t)(kc + kk) * NG + (rem >> 5) * NH + j0 + ((rem & 31) << 2)];
            uint32_t dst = wbase + (uint32_t)(((b * BK + kk) * 512 + (rem << 2)) * 4);
            cp16(dst, src);
        }
        asm volatile("cp.async.commit_group;" ::: "memory");
    };

    issueW(0, 0);

    // Preload entire A slice [Ksp][64] transposed into smem (conflict-free STS;
    // LDG is uncoalesced but tiny and L2-resident).
    {
        const int tot4 = Ksp * 16;               // float4 count (1024 or 2048)
        for (int f = tid; f < tot4; f += 512) {
            int r  = f & 63;
            int jq = f >> 6;                     // 0..Ksp/4-1
            float4 v = *(const float4*)&A[(size_t)r * NH + k0 + jq * 4];
            float* dst = &Asl[(jq * 4) * 64 + r];
            dst[0] = v.x; dst[64] = v.y; dst[128] = v.z; dst[192] = v.w;
        }
    }

    unsigned long long acc[4][8];   // 4 row-pairs x 8 cols
#pragma unroll
    for (int p = 0; p < 4; p++)
#pragma unroll
        for (int c = 0; c < 8; c++) acc[p][c] = 0ull;

    int buf = 0;
    for (int ch = 0; ch < NCH; ch++) {
        asm volatile("cp.async.wait_group 0;" ::: "memory");
        __syncthreads();                         // Ws[buf] ready; buf^1 free
        if (ch + 1 < NCH) issueW(ch + 1, buf ^ 1);

        const float* Ak = Asl + (ch * BK) * 64 + tr * 8;
        const float* Wk = Wsl + (buf * BK) * 512 + tc * 4;
#pragma unroll
        for (int kk = 0; kk < BK; kk++) {
            ulonglong2 a0 = *(const ulonglong2*)(Ak + kk * 64);
            ulonglong2 a1 = *(const ulonglong2*)(Ak + kk * 64 + 4);
            float4 w0 = *(const float4*)(Wk + kk * 512);
            float4 w1 = *(const float4*)(Wk + kk * 512 + 256);
            unsigned long long wd[8] = {
                dup2(w0.x), dup2(w0.y), dup2(w0.z), dup2(w0.w),
                dup2(w1.x), dup2(w1.y), dup2(w1.z), dup2(w1.w)};
            unsigned long long ap[4] = {a0.x, a0.y, a1.x, a1.y};
#pragma unroll
            for (int p = 0; p < 4; p++)
#pragma unroll
                for (int c = 0; c < 8; c++) fma2(acc[p][c], ap[p], wd[c]);
        }
        buf ^= 1;
    }

    // ---- write split partial: 8 rows x 8 cols per thread ----
    {
        float* P = g_part[sp];
#pragma unroll
        for (int p = 0; p < 4; p++) {
            int r0 = tr * 8 + p * 2;
#pragma unroll
            for (int G = 0; G < 2; G++) {
                float lo[4], hi[4];
#pragma unroll
                for (int j = 0; j < 4; j++) unpack2(acc[p][G * 4 + j], lo[j], hi[j]);
                int bc   = G * 256 + tc * 4;          // block gate-col base
                int gcol = (bc >> 7) * NH + j0 + (bc & 127);
                *(float4*)&P[(size_t)r0 * NG + gcol] =
                    make_float4(lo[0], lo[1], lo[2], lo[3]);
                *(float4*)&P[(size_t)(r0 + 1) * NG + gcol] =
                    make_float4(hi[0], hi[1], hi[2], hi[3]);
            }
        }
    }

    // ---- rendezvous: all 16 split blocks of this j-tile ----
    __threadfence();
    __syncthreads();
    if (tid == 0) {
        atomicAdd(&g_cnt[layer][jt], 1);
        const int target = (t + 1) * NSPLIT;     // monotonic: no reset race
        volatile int* cp = &g_cnt[layer][jt];
        while (*cp < target) { __nanosleep(60); }
        __threadfence();
    }
    __syncthreads();

    // ---- cooperative reduction + cell update: block sp takes 4 rows ----
    {
        const int r   = sp * 4 + (tid >> 7);     // 4 rows per block
        const int col = j0 + (tid & 127);        // 128 h-cols
        float gi = 0.f, gf = 0.f, gg = 0.f, go = 0.f;
#pragma unroll
        for (int s = 0; s < NSPLIT; s++) {
            const float* P = g_part[s] + (size_t)r * NG + col;
            gi += P[0]; gf += P[NH]; gg += P[2 * NH]; go += P[3 * NH];
        }
        if (layer == 0) {
            const float* xp = g_xpre + (size_t)t * NB * NG + (size_t)r * NG + col;
            gi += xp[0]; gf += xp[NH]; gg += xp[2 * NH]; go += xp[3 * NH];
        } else {
            const float* bp = biasp + col;
            gi += bp[0]; gf += bp[NH]; gg += bp[2 * NH]; go += bp[3 * NH];
        }
        int ci = r * NH + col;
        float cv = cS[ci];
        float is = sig_(gi), fs = sig_(gf);
        float gt = tanh_(gg), os = sig_(go);
        float cn = fs * cv + is * gt;
        cS[ci]   = cn;
        hOut[ci] = os * tanh_(cn);
    }
}

// ---------------------------------------------------------------------------
// Copy final top-layer hidden state to output. After t = NT-1 (odd), layer1
// wrote g_h1[nxt = 0].
// ---------------------------------------------------------------------------
__global__ void copy_out_kernel(float* __restrict__ out) {
    int i = blockIdx.x * blockDim.x + threadIdx.x;
    if (i < NB * NH) out[i] = g_h1[0][i];
}

// ---------------------------------------------------------------------------
// kernel_launch: graph-capturable, allocation-free, deterministic.
// Inputs: x, Wx0, Wh0, b0, Wx1, Wh1, b1. Output: h1 [64,1024] fp32.
// ---------------------------------------------------------------------------
extern "C" void kernel_launch(void* const* d_in, const int* in_sizes, int n_in,
                              void* d_out, int out_size) {
    const float* x   = (const float*)d_in[0];
    const float* Wx0 = (const float*)d_in[1];
    const float* Wh0 = (const float*)d_in[2];
    const float* b0  = (const float*)d_in[3];
    const float* Wx1 = (const float*)d_in[4];
    const float* Wh1 = (const float*)d_in[5];
    const float* b1  = (const float*)d_in[6];
    float* out = (float*)d_out;

    (void)in_sizes; (void)n_in; (void)out_size;

    constexpr int SMEM_STEP = (128 * 64 + 2 * BK * 512) * 4;  // 64 KB
    cudaFuncSetAttribute(lstm_step_kernel,
                         cudaFuncAttributeMaxDynamicSharedMemorySize, SMEM_STEP);

    init_state_kernel<<<(NB * NH + 255) / 256, 256>>>();

    // Phase 1: all-timestep input projection for layer 0
    precompute_kernel<<<dim3(NG / 64, (NT * NB) / 128), 256>>>(x, Wx0, b0);

    // Phase 2: sequential recurrence, 2 launches per timestep (1 wave each)
    for (int t = 0; t < NT; t++) {
        lstm_step_kernel<<<dim3(NJT, NSPLIT), 512, SMEM_STEP>>>(
            0, t, Wh0, nullptr, nullptr);
        lstm_step_kernel<<<dim3(NJT, NSPLIT), 512, SMEM_STEP>>>(
            1, t, Wx1, Wh1, b1);
    }

    copy_out_kernel<<<(NB * NH + 1023) / 1024, 1024>>>(out);
}

// round 12
// speedup vs baseline: 2.4773x; 1.0223x over previous
#include <cuda_runtime.h>
#include <math.h>
#include <stdint.h>

// Problem dims
constexpr int NB = 64;     // batch
constexpr int NT = 256;    // time
constexpr int ND = 1024;   // input dim
constexpr int NH = 1024;   // hidden
constexpr int NG = 4096;   // 4*NH (gates i,f,g,o)

// Step-kernel tiling: block = 64 rows x 256 gate-cols (= 64 h-cols x 4 gates),
// 512 threads, 8x4 per thread (32 acc regs), BK=16 cp.async double-buffered,
// split-K=8. grid (16 j-tiles, 8 splits) = 128 blocks = one wave.
constexpr int JT     = 64;       // h-columns per block tile
constexpr int NJT    = NH / JT;  // 16 j-tiles
constexpr int NSPLIT = 8;        // K splits per layer-step
constexpr int BK     = 16;       // k-chunk for W streaming

// ---------------------------------------------------------------------------
// Scratch state (device globals: allocation-free per harness rules)
// ---------------------------------------------------------------------------
__device__ float g_xpre[(size_t)NT * NB * NG];  // x @ Wx0 + b0  (256 MB)
__device__ float g_h0[2][NB * NH];              // ping-pong by t parity
__device__ float g_h1[2][NB * NH];
__device__ float g_c0[NB * NH];
__device__ float g_c1[NB * NH];
__device__ float g_part[NSPLIT][NB * NG];       // split-K partial gates (8 MB)
__device__ int   g_cnt[2][NJT];                 // monotonic per (layer,jtile)

// ---------------------------------------------------------------------------
// Packed f32x2 helpers (Blackwell packed fp32: 2x FFMA throughput)
// ---------------------------------------------------------------------------
__device__ __forceinline__ unsigned long long dup2(float v) {
    unsigned long long r;
    asm("mov.b64 %0, {%1, %1};" : "=l"(r) : "f"(v));
    return r;
}
__device__ __forceinline__ void fma2(unsigned long long& acc,
                                     unsigned long long a, unsigned long long b) {
    asm("fma.rn.f32x2 %0, %1, %2, %0;" : "+l"(acc) : "l"(a), "l"(b));
}
__device__ __forceinline__ void unpack2(unsigned long long v, float& lo, float& hi) {
    asm("mov.b64 {%0, %1}, %2;" : "=f"(lo), "=f"(hi) : "l"(v));
}
__device__ __forceinline__ unsigned long long pack2(float lo, float hi) {
    unsigned long long r;
    asm("mov.b64 %0, {%1, %2};" : "=l"(r) : "f"(lo), "f"(hi));
    return r;
}
__device__ __forceinline__ float sig_(float x)  { return 1.0f / (1.0f + __expf(-x)); }
__device__ __forceinline__ float tanh_(float x) {
    float e = __expf(2.0f * x);            // inf-safe: e=inf -> 1, e=0 -> -1
    return 1.0f - 2.0f / (e + 1.0f);
}
__device__ __forceinline__ void cp16(uint32_t dst, const void* src) {
    asm volatile("cp.async.cg.shared.global [%0], [%1], 16;" :: "r"(dst), "l"(src));
}

// ---------------------------------------------------------------------------
// Zero recurrent state + counters (graph replays reuse device globals)
// ---------------------------------------------------------------------------
__global__ void init_state_kernel() {
    int i = blockIdx.x * blockDim.x + threadIdx.x;
    if (i < NB * NH) {
        g_h0[0][i] = 0.f; g_h0[1][i] = 0.f;
        g_h1[0][i] = 0.f; g_h1[1][i] = 0.f;
        g_c0[i] = 0.f;    g_c1[i] = 0.f;
    }
    if (i < 2 * NJT) ((int*)g_cnt)[i] = 0;
}

// ---------------------------------------------------------------------------
// Precompute: Xpre[(t*NB+b)][n] = sum_k x[b][t][k] * Wx0[k][n] + b0[n]
// (unchanged from prior passing rounds)
// ---------------------------------------------------------------------------
__global__ __launch_bounds__(256) void precompute_kernel(
    const float* __restrict__ x, const float* __restrict__ Wx0,
    const float* __restrict__ b0)
{
    constexpr int PBK = 16;
    __shared__ float As[PBK][132];
    __shared__ float Ws[PBK][64];

    const int tid = threadIdx.x;
    const int tc = tid & 15;
    const int tr = tid >> 4;
    const int col0 = blockIdx.x * 64;
    const int row0 = blockIdx.y * 128;

    unsigned long long acc[8][2];
#pragma unroll
    for (int i = 0; i < 8; i++) { acc[i][0] = 0ull; acc[i][1] = 0ull; }

    for (int k0 = 0; k0 < ND; k0 += PBK) {
#pragma unroll
        for (int i = 0; i < 2; i++) {
            int idx = tid + i * 256;
            int r   = idx & 127;
            int kq  = (idx >> 7) << 2;
            int grow = row0 + r;
            int tt = grow >> 6;
            int bb = grow & 63;
            float4 v = *(const float4*)&x[((size_t)bb * NT + tt) * ND + k0 + kq];
            As[kq + 0][r] = v.x; As[kq + 1][r] = v.y;
            As[kq + 2][r] = v.z; As[kq + 3][r] = v.w;
        }
        {
            int kk = tid >> 4;
            int nq = (tid & 15) << 2;
            *(float4*)&Ws[kk][nq] =
                *(const float4*)&Wx0[(size_t)(k0 + kk) * NG + col0 + nq];
        }
        __syncthreads();

#pragma unroll
        for (int kk = 0; kk < PBK; kk++) {
            float4 a0 = *(const float4*)&As[kk][tr * 8];
            float4 a1 = *(const float4*)&As[kk][tr * 8 + 4];
            float4 wv = *(const float4*)&Ws[kk][tc * 4];
            unsigned long long w01 = pack2(wv.x, wv.y);
            unsigned long long w23 = pack2(wv.z, wv.w);
            float ar[8] = {a0.x, a0.y, a0.z, a0.w, a1.x, a1.y, a1.z, a1.w};
#pragma unroll
            for (int i = 0; i < 8; i++) {
                unsigned long long ad = dup2(ar[i]);
                fma2(acc[i][0], ad, w01);
                fma2(acc[i][1], ad, w23);
            }
        }
        __syncthreads();
    }

    const int c = col0 + tc * 4;
    float4 bb4 = *(const float4*)&b0[c];
#pragma unroll
    for (int i = 0; i < 8; i++) {
        int grow = row0 + tr * 8 + i;
        float v0, v1, v2, v3;
        unpack2(acc[i][0], v0, v1);
        unpack2(acc[i][1], v2, v3);
        float4 o;
        o.x = v0 + bb4.x; o.y = v1 + bb4.y; o.z = v2 + bb4.z; o.w = v3 + bb4.w;
        *(float4*)&g_xpre[(size_t)grow * NG + c] = o;
    }
}

// ---------------------------------------------------------------------------
// One LSTM layer step: split-K GEMM + cooperative j-tile reduction.
//   layer 0: gates = Xpre[t] + h0_prev @ Wh0            (K=1024, 8 splits x 128)
//   layer 1: gates = b1 + h0_new @ Wx1 + h1_prev @ Wh1  (K=2048, 8 splits x 256)
// grid (16 j-tiles, 8 splits) = 128 blocks, 512 thr (single wave, 4 warps/SMSP).
// A slice preloaded to smem [k][row] once; W streamed with cp.async (BK=16 x2).
// Inner loop is explicitly software-pipelined (prefetch kk+1 LDS before FMAs).
// After partial writes, all 8 blocks of a j-tile rendezvous on a monotonic
// counter and each reduces a disjoint 8-row slice (deterministic order).
// ---------------------------------------------------------------------------
__global__ __launch_bounds__(512, 1) void lstm_step_kernel(
    int layer, int t,
    const float* __restrict__ W1p,   // Wh0 (L0) or Wx1 (L1)
    const float* __restrict__ W2p,   // Wh1 (L1) or null
    const float* __restrict__ biasp) // b1 (L1) or null
{
    extern __shared__ float sdyn[];
    float* Asl = sdyn;                       // [Ksp<=256][64]   (64 KB max)
    float* Wsl = sdyn + 256 * 64;            // [2][BK][256]     (32 KB)

    const int tid = threadIdx.x;     // 512
    const int tc  = tid & 63;        // 64 col-threads * 4 cols = 256
    const int tr  = tid >> 6;        // 8 row-threads * 8 rows = 64
    const int jt  = blockIdx.x;      // 0..15
    const int sp  = blockIdx.y;      // 0..7
    const int j0  = jt * JT;         // h-col base

    const int cur = t & 1, nxt = cur ^ 1;
    const float* A;
    const float* W;
    int k0, Ksp;
    float* cS; float* hOut;
    if (layer == 0) {
        Ksp = ND / NSPLIT;                       // 128
        A = g_h0[cur]; W = W1p; k0 = sp * Ksp;
        cS = g_c0; hOut = g_h0[nxt];
    } else {
        Ksp = 2048 / NSPLIT;                     // 256
        if (sp < 4) { A = g_h0[nxt]; W = W1p; k0 = sp * Ksp; }        // h0 (cur t)
        else        { A = g_h1[cur]; W = W2p; k0 = (sp - 4) * Ksp; }  // h1 (prev t)
        cS = g_c1; hOut = g_h1[nxt];
    }
    const int NCH = Ksp / BK;   // 8 (L0) or 16 (L1)

    const uint32_t wbase = (uint32_t)__cvta_generic_to_shared(Wsl);

    // issue cp.async for W chunk ch into buffer b: 16 k x 256 cols = 1024 float4
    auto issueW = [&](int ch, int b) {
        const int kc = k0 + ch * BK;
#pragma unroll
        for (int i = 0; i < 2; i++) {
            int idx = tid + i * 512;             // 0..1023
            int kk  = idx >> 6;                  // 0..15
            int rem = idx & 63;                  // float4 group within 256 cols
            const float* src =
                &W[(size_t)(kc + kk) * NG + (rem >> 4) * NH + j0 + ((rem & 15) << 2)];
            uint32_t dst = wbase + (uint32_t)(((b * BK + kk) * 256 + (rem << 2)) * 4);
            cp16(dst, src);
        }
        asm volatile("cp.async.commit_group;" ::: "memory");
    };

    issueW(0, 0);

    // Preload entire A slice [Ksp][64] transposed into smem (conflict-free STS).
    {
        const int tot4 = Ksp * 16;               // float4 count (2048 or 4096)
        for (int f = tid; f < tot4; f += 512) {
            int r  = f & 63;
            int jq = f >> 6;                     // 0..Ksp/4-1
            float4 v = *(const float4*)&A[(size_t)r * NH + k0 + jq * 4];
            float* dst = &Asl[(jq * 4) * 64 + r];
            dst[0] = v.x; dst[64] = v.y; dst[128] = v.z; dst[192] = v.w;
        }
    }

    unsigned long long acc[4][4];   // 4 row-pairs x 4 cols = 32 regs
#pragma unroll
    for (int p = 0; p < 4; p++)
#pragma unroll
        for (int c = 0; c < 4; c++) acc[p][c] = 0ull;

    int buf = 0;
    for (int ch = 0; ch < NCH; ch++) {
        asm volatile("cp.async.wait_group 0;" ::: "memory");
        __syncthreads();                         // Ws[buf] ready; buf^1 free
        if (ch + 1 < NCH) issueW(ch + 1, buf ^ 1);

        const float* Ak = Asl + (ch * BK) * 64 + tr * 8;
        const float* Wk = Wsl + (buf * BK) * 256 + tc * 4;

        // software-pipelined: operands for kk preloaded during kk-1's FMAs
        ulonglong2 a0 = *(const ulonglong2*)(Ak);
        ulonglong2 a1 = *(const ulonglong2*)(Ak + 4);
        float4     w  = *(const float4*)(Wk);
#pragma unroll
        for (int kk = 0; kk < BK; kk++) {
            ulonglong2 b0, b1; float4 wn;
            if (kk + 1 < BK) {
                b0 = *(const ulonglong2*)(Ak + (kk + 1) * 64);
                b1 = *(const ulonglong2*)(Ak + (kk + 1) * 64 + 4);
                wn = *(const float4*)(Wk + (kk + 1) * 256);
            }
            unsigned long long wd[4] = {dup2(w.x), dup2(w.y), dup2(w.z), dup2(w.w)};
            unsigned long long ap[4] = {a0.x, a0.y, a1.x, a1.y};
#pragma unroll
            for (int p = 0; p < 4; p++)
#pragma unroll
                for (int c = 0; c < 4; c++) fma2(acc[p][c], ap[p], wd[c]);
            a0 = b0; a1 = b1; w = wn;
        }
        buf ^= 1;
    }

    // ---- write split partial: 8 rows x 4 cols per thread ----
    {
        float* P = g_part[sp];
        const int bc   = tc * 4;                         // within one gate (64-mult)
        const int gcol = (bc >> 6) * NH + j0 + (bc & 63);
#pragma unroll
        for (int p = 0; p < 4; p++) {
            int r0 = tr * 8 + p * 2;
            float lo[4], hi[4];
#pragma unroll
            for (int j = 0; j < 4; j++) unpack2(acc[p][j], lo[j], hi[j]);
            *(float4*)&P[(size_t)r0 * NG + gcol] =
                make_float4(lo[0], lo[1], lo[2], lo[3]);
            *(float4*)&P[(size_t)(r0 + 1) * NG + gcol] =
                make_float4(hi[0], hi[1], hi[2], hi[3]);
        }
    }

    // ---- rendezvous: all 8 split blocks of this j-tile ----
    __threadfence();
    __syncthreads();
    if (tid == 0) {
        atomicAdd(&g_cnt[layer][jt], 1);
        const int target = (t + 1) * NSPLIT;     // monotonic: no reset race
        volatile int* cp = &g_cnt[layer][jt];
        while (*cp < target) { __nanosleep(60); }
        __threadfence();
    }
    __syncthreads();

    // ---- cooperative reduction + cell update: block sp takes 8 rows ----
    {
        const int r   = sp * 8 + (tid >> 6);     // 8 rows per block
        const int col = j0 + (tid & 63);         // 64 h-cols
        float gi = 0.f, gf = 0.f, gg = 0.f, go = 0.f;
#pragma unroll
        for (int s = 0; s < NSPLIT; s++) {
            const float* P = g_part[s] + (size_t)r * NG + col;
            gi += P[0]; gf += P[NH]; gg += P[2 * NH]; go += P[3 * NH];
        }
        if (layer == 0) {
            const float* xp = g_xpre + (size_t)t * NB * NG + (size_t)r * NG + col;
            gi += xp[0]; gf += xp[NH]; gg += xp[2 * NH]; go += xp[3 * NH];
        } else {
            const float* bp = biasp + col;
            gi += bp[0]; gf += bp[NH]; gg += bp[2 * NH]; go += bp[3 * NH];
        }
        int ci = r * NH + col;
        float cv = cS[ci];
        float is = sig_(gi), fs = sig_(gf);
        float gt = tanh_(gg), os = sig_(go);
        float cn = fs * cv + is * gt;
        cS[ci]   = cn;
        hOut[ci] = os * tanh_(cn);
    }
}

// ---------------------------------------------------------------------------
// Copy final top-layer hidden state to output. After t = NT-1 (odd), layer1
// wrote g_h1[nxt = 0].
// ---------------------------------------------------------------------------
__global__ void copy_out_kernel(float* __restrict__ out) {
    int i = blockIdx.x * blockDim.x + threadIdx.x;
    if (i < NB * NH) out[i] = g_h1[0][i];
}

// ---------------------------------------------------------------------------
// kernel_launch: graph-capturable, allocation-free, deterministic.
// Inputs: x, Wx0, Wh0, b0, Wx1, Wh1, b1. Output: h1 [64,1024] fp32.
// ---------------------------------------------------------------------------
extern "C" void kernel_launch(void* const* d_in, const int* in_sizes, int n_in,
                              void* d_out, int out_size) {
    const float* x   = (const float*)d_in[0];
    const float* Wx0 = (const float*)d_in[1];
    const float* Wh0 = (const float*)d_in[2];
    const float* b0  = (const float*)d_in[3];
    const float* Wx1 = (const float*)d_in[4];
    const float* Wh1 = (const float*)d_in[5];
    const float* b1  = (const float*)d_in[6];
    float* out = (float*)d_out;

    (void)in_sizes; (void)n_in; (void)out_size;

    constexpr int SMEM_STEP = (256 * 64 + 2 * BK * 256) * 4;  // 96 KB
    cudaFuncSetAttribute(lstm_step_kernel,
                         cudaFuncAttributeMaxDynamicSharedMemorySize, SMEM_STEP);

    init_state_kernel<<<(NB * NH + 255) / 256, 256>>>();

    // Phase 1: all-timestep input projection for layer 0
    precompute_kernel<<<dim3(NG / 64, (NT * NB) / 128), 256>>>(x, Wx0, b0);

    // Phase 2: sequential recurrence, 2 launches per timestep (1 wave each)
    for (int t = 0; t < NT; t++) {
        lstm_step_kernel<<<dim3(NJT, NSPLIT), 512, SMEM_STEP>>>(
            0, t, Wh0, nullptr, nullptr);
        lstm_step_kernel<<<dim3(NJT, NSPLIT), 512, SMEM_STEP>>>(
            1, t, Wx1, Wh1, b1);
    }

    copy_out_kernel<<<(NB * NH + 1023) / 1024, 1024>>>(out);
}